// round 5
// baseline (speedup 1.0000x reference)
#include <cuda_runtime.h>

#define NS 10
#define ND 32
#define NL 4
#define NB 1024

typedef unsigned long long u64;

// ---- packed f32x2 helpers (sm_103a) ----
__device__ __forceinline__ u64 ffma2(u64 a, u64 b, u64 c) {
    u64 d;
    asm("fma.rn.f32x2 %0, %1, %2, %3;" : "=l"(d) : "l"(a), "l"(b), "l"(c));
    return d;
}
__device__ __forceinline__ u64 fadd2(u64 a, u64 b) {
    u64 d;
    asm("add.rn.f32x2 %0, %1, %2;" : "=l"(d) : "l"(a), "l"(b));
    return d;
}
__device__ __forceinline__ u64 pack2(float lo, float hi) {
    u64 d;
    asm("mov.b64 %0, {%1, %2};" : "=l"(d) : "f"(lo), "f"(hi));
    return d;
}
__device__ __forceinline__ float hsum2(u64 v) {
    float lo, hi;
    asm("mov.b64 {%0, %1}, %2;" : "=f"(lo), "=f"(hi) : "l"(v));
    return lo + hi;
}

__global__ __launch_bounds__(256, 3)
void dendrite_kernel(const float* __restrict__ x,
                     const float* __restrict__ k,
                     const float* __restrict__ w,
                     const float* __restrict__ q,
                     const float* __restrict__ dend_w,
                     const float* __restrict__ dend_b,
                     const float* __restrict__ lin_w,
                     const float* __restrict__ lin_b,
                     const float* __restrict__ final_w,
                     const float* __restrict__ final_b,
                     const float* __restrict__ ks,
                     float* __restrict__ out)
{
    // dend_w per-layer with a zero at v=0 so the excluded empty subset drops out
    __shared__ __align__(16) float sdw[NL * 1024];
    __shared__ float part[NL][ND];   // half-1 partial sums
    __shared__ float sred[NL];

    const int tid  = threadIdx.x;
    const int wid  = tid >> 5;
    const int l    = wid & 3;        // layer
    const int half = wid >> 2;       // h-range half: 0 -> h 0..15, 1 -> h 16..31
    const int d    = tid & 31;       // dendrite (lane)
    const int b    = blockIdx.x;     // one batch element per block

    // Stage dend_w into shared (overlaps with per-thread setup below)
    for (int i = tid; i < NL * 1024; i += 256) {
        int ll = i >> 10, v = i & 1023;
        sdw[i] = v ? dend_w[ll * 1023 + v - 1] : 0.0f;
    }

    // s_i = sigmoid(k * (w * x - q)), i = 0..9
    const int base = (l * ND + d) * NS;
    float s[NS];
    #pragma unroll
    for (int i = 0; i < NS; ++i) {
        float z = k[base + i] * (w[base + i] * x[b * NS + i] - q[base + i]);
        s[i] = 1.0f / (1.0f + __expf(-z));
    }

    // Subset products of the low-5 mask bits: bit p of lo -> s[9-p]
    float Plo[32];
    Plo[0] = 1.0f;
    #pragma unroll
    for (int bit = 0; bit < 5; ++bit) {
        const float sv = s[9 - bit];
        #pragma unroll
        for (int u = 0; u < (1 << bit); ++u)
            Plo[(1 << bit) + u] = Plo[u] * sv;
    }
    u64 Pp[16];
    #pragma unroll
    for (int u = 0; u < 16; ++u) Pp[u] = pack2(Plo[2 * u], Plo[2 * u + 1]);

    // h-tree factors: bit p of h -> s[4-p]; bit 4 (half select) -> s[0]
    float sH[4];
    #pragma unroll
    for (int p = 0; p < 4; ++p) sH[p] = s[4 - p];
    const float s0 = s[0];

    __syncthreads();

    // Mainloop: this warp's 16 h-rows. g_h = sum_lo sdw[32h+lo]*Plo[lo];
    // partial = sum_h Phi'[h] g_h via a 4-level binary-counter Horner tree.
    const ulonglong2* row =
        reinterpret_cast<const ulonglong2*>(sdw + (l << 10)) + half * (16 * 8);
    float lvl[4];
    float res = 0.0f;
    #pragma unroll
    for (int h = 0; h < 16; ++h) {
        u64 t0 = 0ULL, t1 = 0ULL;
        #pragma unroll
        for (int j = 0; j < 8; ++j) {
            ulonglong2 dv = row[h * 8 + j];   // broadcast LDS.128
            t0 = ffma2(dv.x, Pp[2 * j],     t0);
            t1 = ffma2(dv.y, Pp[2 * j + 1], t1);
        }
        float v = hsum2(fadd2(t0, t1));
        bool done = false;
        #pragma unroll
        for (int p = 0; p < 4; ++p) {
            if (!done) {
                if ((h >> p) & 1) {
                    v = fmaf(v, sH[p], lvl[p]);
                } else {
                    lvl[p] = v;
                    done = true;
                }
            }
        }
        if (h == 15) res = v;
    }

    if (half) part[l][d] = res * s0;   // h>=16 rows carry the extra s[0] factor
    __syncthreads();

    if (!half) {
        float dend = res + part[l][d] + dend_b[l];
        float v = dend * lin_w[l * ND + d];
        #pragma unroll
        for (int off = 16; off; off >>= 1)
            v += __shfl_xor_sync(0xffffffffu, v, off);
        if (d == 0) sred[l] = (v + lin_b[l]) * final_w[l];
    }
    __syncthreads();
    if (tid == 0) {
        float fin = sred[0] + sred[1] + sred[2] + sred[3] + final_b[0];
        out[b] = 1.0f / (1.0f + __expf(-ks[0] * fin));
    }
}

extern "C" void kernel_launch(void* const* d_in, const int* in_sizes, int n_in,
                              void* d_out, int out_size) {
    const float* x       = (const float*)d_in[0];
    const float* k       = (const float*)d_in[1];
    const float* w       = (const float*)d_in[2];
    const float* q       = (const float*)d_in[3];
    const float* dend_w  = (const float*)d_in[4];
    const float* dend_b  = (const float*)d_in[5];
    const float* lin_w   = (const float*)d_in[6];
    const float* lin_b   = (const float*)d_in[7];
    const float* final_w = (const float*)d_in[8];
    const float* final_b = (const float*)d_in[9];
    const float* ks      = (const float*)d_in[10];
    float* out = (float*)d_out;
    dendrite_kernel<<<NB, 256>>>(x, k, w, q, dend_w, dend_b,
                                 lin_w, lin_b, final_w, final_b, ks, out);
}

// round 7
// speedup vs baseline: 1.3401x; 1.3401x over previous
#include <cuda_runtime.h>

#define NS 10
#define ND 32
#define NL 4
#define NB 1024
#define BPT 2

typedef unsigned long long u64;

// ---- packed f32x2 helpers (sm_103a) ----
__device__ __forceinline__ u64 ffma2(u64 a, u64 b, u64 c) {
    u64 d;
    asm("fma.rn.f32x2 %0, %1, %2, %3;" : "=l"(d) : "l"(a), "l"(b), "l"(c));
    return d;
}
__device__ __forceinline__ u64 fadd2(u64 a, u64 b) {
    u64 d;
    asm("add.rn.f32x2 %0, %1, %2;" : "=l"(d) : "l"(a), "l"(b));
    return d;
}
__device__ __forceinline__ u64 pack2(float lo, float hi) {
    u64 d;
    asm("mov.b64 %0, {%1, %2};" : "=l"(d) : "f"(lo), "f"(hi));
    return d;
}
__device__ __forceinline__ float hsum2(u64 v) {
    float lo, hi;
    asm("mov.b64 {%0, %1}, %2;" : "=f"(lo), "=f"(hi) : "l"(v));
    return lo + hi;
}
__device__ __forceinline__ void unpack2(u64 v, float& lo, float& hi) {
    asm("mov.b64 {%0, %1}, %2;" : "=f"(lo), "=f"(hi) : "l"(v));
}

__global__ __launch_bounds__(128, 3)
void dendrite_kernel(const float* __restrict__ x,
                     const float* __restrict__ k,
                     const float* __restrict__ w,
                     const float* __restrict__ q,
                     const float* __restrict__ dend_w,
                     const float* __restrict__ dend_b,
                     const float* __restrict__ lin_w,
                     const float* __restrict__ lin_b,
                     const float* __restrict__ final_w,
                     const float* __restrict__ final_b,
                     const float* __restrict__ ks,
                     float* __restrict__ out)
{
    // dend_w per-layer, zero at v=0 so the excluded empty subset drops out
    __shared__ __align__(16) float sdw[NL * 1024];
    __shared__ float sred[BPT][NL];

    const int tid = threadIdx.x;
    const int l   = tid >> 5;        // warp == layer
    const int d   = tid & 31;        // lane == dendrite
    const int b0  = blockIdx.x * BPT;

    for (int i = tid; i < NL * 1024; i += 128) {
        int ll = i >> 10, v = i & 1023;
        sdw[i] = v ? dend_w[ll * 1023 + v - 1] : 0.0f;
    }

    // ---- setup: s_i = sigmoid(k*(w*x - q)) for both batch elements ----
    const int base = (l * ND + d) * NS;
    float sA[NS], sB[NS];
    #pragma unroll
    for (int i = 0; i < NS; ++i) {
        const float ki = k[base + i], wi = w[base + i], qi = q[base + i];
        float zA = ki * (wi * x[b0 * NS + i] - qi);
        float zB = ki * (wi * x[(b0 + 1) * NS + i] - qi);
        sA[i] = 1.0f / (1.0f + __expf(-zA));
        sB[i] = 1.0f / (1.0f + __expf(-zB));
    }

    // Subset products of low-5 mask bits (bit p of lo -> s[9-p]), packed per b
    u64 PpA[16], PpB[16];
    {
        float PloA[32], PloB[32];
        PloA[0] = 1.0f; PloB[0] = 1.0f;
        #pragma unroll
        for (int bit = 0; bit < 5; ++bit) {
            const float va = sA[9 - bit], vb = sB[9 - bit];
            #pragma unroll
            for (int u = 0; u < (1 << bit); ++u) {
                PloA[(1 << bit) + u] = PloA[u] * va;
                PloB[(1 << bit) + u] = PloB[u] * vb;
            }
        }
        #pragma unroll
        for (int u = 0; u < 16; ++u) {
            PpA[u] = pack2(PloA[2 * u], PloA[2 * u + 1]);
            PpB[u] = pack2(PloB[2 * u], PloB[2 * u + 1]);
        }
    }

    // h-tree factors (bit p of h -> s[4-p]), packed (A,B)
    u64 sHp[5];
    #pragma unroll
    for (int p = 0; p < 5; ++p) sHp[p] = pack2(sA[4 - p], sB[4 - p]);

    __syncthreads();

    // ---- mainloop, software-pipelined at quad (4x LDS.128) granularity ----
    const ulonglong2* __restrict__ row =
        reinterpret_cast<const ulonglong2*>(sdw + (l << 10));

    u64 lvl[5];
    u64 res2 = 0ULL;

    // prime: first half of h=0
    ulonglong2 c0 = row[0], c1 = row[1], c2 = row[2], c3 = row[3];

    #pragma unroll
    for (int h = 0; h < 32; ++h) {
        // issue loads for second half of row h
        ulonglong2 n0 = row[h * 8 + 4], n1 = row[h * 8 + 5],
                   n2 = row[h * 8 + 6], n3 = row[h * 8 + 7];

        u64 t0a = 0ULL, t1a = 0ULL, t0b = 0ULL, t1b = 0ULL;
        // consume current quad (j = 0..3 -> Pp[0..7])
        t0a = ffma2(c0.x, PpA[0], t0a);  t0b = ffma2(c0.x, PpB[0], t0b);
        t1a = ffma2(c0.y, PpA[1], t1a);  t1b = ffma2(c0.y, PpB[1], t1b);
        t0a = ffma2(c1.x, PpA[2], t0a);  t0b = ffma2(c1.x, PpB[2], t0b);
        t1a = ffma2(c1.y, PpA[3], t1a);  t1b = ffma2(c1.y, PpB[3], t1b);
        t0a = ffma2(c2.x, PpA[4], t0a);  t0b = ffma2(c2.x, PpB[4], t0b);
        t1a = ffma2(c2.y, PpA[5], t1a);  t1b = ffma2(c2.y, PpB[5], t1b);
        t0a = ffma2(c3.x, PpA[6], t0a);  t0b = ffma2(c3.x, PpB[6], t0b);
        t1a = ffma2(c3.y, PpA[7], t1a);  t1b = ffma2(c3.y, PpB[7], t1b);

        // issue loads for first half of row h+1 (dead for h==31 but in-bounds? guard)
        if (h < 31) {
            c0 = row[(h + 1) * 8 + 0]; c1 = row[(h + 1) * 8 + 1];
            c2 = row[(h + 1) * 8 + 2]; c3 = row[(h + 1) * 8 + 3];
        }

        // consume second-half quad (j = 4..7 -> Pp[8..15])
        t0a = ffma2(n0.x, PpA[8],  t0a);  t0b = ffma2(n0.x, PpB[8],  t0b);
        t1a = ffma2(n0.y, PpA[9],  t1a);  t1b = ffma2(n0.y, PpB[9],  t1b);
        t0a = ffma2(n1.x, PpA[10], t0a);  t0b = ffma2(n1.x, PpB[10], t0b);
        t1a = ffma2(n1.y, PpA[11], t1a);  t1b = ffma2(n1.y, PpB[11], t1b);
        t0a = ffma2(n2.x, PpA[12], t0a);  t0b = ffma2(n2.x, PpB[12], t0b);
        t1a = ffma2(n2.y, PpA[13], t1a);  t1b = ffma2(n2.y, PpB[13], t1b);
        t0a = ffma2(n3.x, PpA[14], t0a);  t0b = ffma2(n3.x, PpB[14], t0b);
        t1a = ffma2(n3.y, PpA[15], t1a);  t1b = ffma2(n3.y, PpB[15], t1b);

        // g_h for both b, packed
        u64 v2 = pack2(hsum2(fadd2(t0a, t1a)), hsum2(fadd2(t0b, t1b)));

        // streaming binary-counter Horner tree over h (packed A,B)
        bool done = false;
        #pragma unroll
        for (int p = 0; p < 5; ++p) {
            if (!done) {
                if ((h >> p) & 1) {
                    v2 = ffma2(v2, sHp[p], lvl[p]);
                } else {
                    lvl[p] = v2;
                    done = true;
                }
            }
        }
        if (h == 31) res2 = v2;
    }

    float resA, resB;
    unpack2(res2, resA, resB);

    // ---- epilogue: Linear(D,1) warp reduce, Linear(L,1), sigmoid ----
    const float lw = lin_w[l * ND + d];
    const float db = dend_b[l];
    float vA = (resA + db) * lw;
    float vB = (resB + db) * lw;
    #pragma unroll
    for (int off = 16; off; off >>= 1) {
        vA += __shfl_xor_sync(0xffffffffu, vA, off);
        vB += __shfl_xor_sync(0xffffffffu, vB, off);
    }
    if (d == 0) {
        const float fw = final_w[l], lb = lin_b[l];
        sred[0][l] = (vA + lb) * fw;
        sred[1][l] = (vB + lb) * fw;
    }
    __syncthreads();
    if (tid < BPT) {
        float fin = sred[tid][0] + sred[tid][1] + sred[tid][2] + sred[tid][3] + final_b[0];
        out[b0 + tid] = 1.0f / (1.0f + __expf(-ks[0] * fin));
    }
}

extern "C" void kernel_launch(void* const* d_in, const int* in_sizes, int n_in,
                              void* d_out, int out_size) {
    const float* x       = (const float*)d_in[0];
    const float* k       = (const float*)d_in[1];
    const float* w       = (const float*)d_in[2];
    const float* q       = (const float*)d_in[3];
    const float* dend_w  = (const float*)d_in[4];
    const float* dend_b  = (const float*)d_in[5];
    const float* lin_w   = (const float*)d_in[6];
    const float* lin_b   = (const float*)d_in[7];
    const float* final_w = (const float*)d_in[8];
    const float* final_b = (const float*)d_in[9];
    const float* ks      = (const float*)d_in[10];
    float* out = (float*)d_out;
    dendrite_kernel<<<NB / BPT, 128>>>(x, k, w, q, dend_w, dend_b,
                                       lin_w, lin_b, final_w, final_b, ks, out);
}